// round 6
// baseline (speedup 1.0000x reference)
#include <cuda_runtime.h>
#include <math.h>

#define NH 2
#define NB 2048
#define NM 64
#define ND 16
#define NREL 32

// Q[b][r][j] = sum_i R[r][i][j] * item_e[b][i]   -> [2048][32][16] floats = 4MB
__device__ float4 Q_buf[NB * NREL * ND / 4];

// ---------------- Kernel 1: per-item relation projections ----------------
// 512 blocks x 128 threads; each block handles 4 consecutive b.
// thread t: r = t>>2 (0..31), jg = t&3 (float4 column group).
__global__ __launch_bounds__(128)
void qprep_kernel(const int* __restrict__ items,
                  const float* __restrict__ ent,
                  const float* __restrict__ relm)
{
    const int b0 = blockIdx.x * 4;
    const int t  = threadIdx.x;
    const int r  = t >> 2;
    const int jg = t & 3;

    __shared__ __align__(16) float item_s[4][ND];

    if (t < 64) {
        const int bb = t >> 4;
        const int d  = t & 15;
        item_s[bb][d] = ent[(size_t)items[b0 + bb] * ND + d];
    }
    __syncthreads();

    const float4* relm4 = (const float4*)relm;

    float4 acc[4];
    #pragma unroll
    for (int bb = 0; bb < 4; bb++) acc[bb] = make_float4(0.f, 0.f, 0.f, 0.f);

    #pragma unroll
    for (int i = 0; i < ND; i++) {
        float4 Rv = relm4[r * 64 + i * 4 + jg];   // R[r][i][jg*4 .. +3]
        #pragma unroll
        for (int bb = 0; bb < 4; bb++) {
            float s = item_s[bb][i];
            acc[bb].x += s * Rv.x;
            acc[bb].y += s * Rv.y;
            acc[bb].z += s * Rv.z;
            acc[bb].w += s * Rv.w;
        }
    }

    #pragma unroll
    for (int bb = 0; bb < 4; bb++) {
        Q_buf[(size_t)(b0 + bb) * 128 + t] = acc[bb];   // t = r*4+jg -> coalesced
    }
}

// ---------------- Kernel 2: gathers + softmax + output ----------------
// 2048 blocks x 128 threads. Quad (4 threads) per slot.
// All indices staged first; all 8 global gathers issued back-to-back (MLP=8).
__global__ __launch_bounds__(128)
void ripple_kernel(const int* __restrict__ items,
                   const int* __restrict__ heads,
                   const int* __restrict__ rels,
                   const int* __restrict__ tails,
                   const float* __restrict__ ent,
                   float* __restrict__ out)
{
    const int b    = blockIdx.x;
    const int t    = threadIdx.x;      // 0..127
    const int lane = t & 31;
    const int wid  = t >> 5;
    const int sub  = t & 3;            // position within quad
    const int quad = t >> 2;           // 0..31

    __shared__ __align__(16) float item_s[ND];
    __shared__ __align__(16) float4 q_s[NREL * 4];   // Q[b]: [r][jg]
    __shared__ int   hidx_s[NH * NM];
    __shared__ int   ridx_s[NH * NM];
    __shared__ int   tidx_s[NH * NM];
    __shared__ float logit_s[NH * NM];
    __shared__ float td_s[NH * NM];
    __shared__ float red_s[8];

    // ---- stage item emb + Q[b] + all 384 indices (all coalesced) ----
    if (t < ND) item_s[t] = ent[(size_t)items[b] * ND + t];
    q_s[t] = Q_buf[(size_t)b * 128 + t];
    {
        const int hop_t = t >> 6;
        const int m_t   = t & 63;
        const int g     = hop_t * (NB * NM) + b * NM + m_t;
        hidx_s[t] = heads[g];
        ridx_s[t] = rels[g];
        tidx_s[t] = tails[g];
    }
    __syncthreads();

    const float4* ent4 = (const float4*)ent;
    const float4  iv   = ((const float4*)item_s)[sub];

    // ---- read my 4 slots' indices (quad-broadcast LDS) ----
    int hidx[4], ridx[4], tidx[4];
    #pragma unroll
    for (int p = 0; p < 4; p++) {
        const int s = p * 32 + quad;
        hidx[p] = hidx_s[s];
        ridx[p] = ridx_s[s];
        tidx[p] = tidx_s[s];
    }

    // ---- issue all gathers back-to-back: 8 global + 4 shared, independent ----
    float4 hv[4], tv[4], qv[4];
    #pragma unroll
    for (int p = 0; p < 4; p++) hv[p] = ent4[(size_t)hidx[p] * 4 + sub];
    #pragma unroll
    for (int p = 0; p < 4; p++) tv[p] = ent4[(size_t)tidx[p] * 4 + sub];
    #pragma unroll
    for (int p = 0; p < 4; p++) qv[p] = q_s[ridx[p] * 4 + sub];

    // ---- compute + quad-reduce + write per-slot results ----
    #pragma unroll
    for (int p = 0; p < 4; p++) {
        float pl = qv[p].x * hv[p].x + qv[p].y * hv[p].y
                 + qv[p].z * hv[p].z + qv[p].w * hv[p].w;
        float pt = iv.x * tv[p].x + iv.y * tv[p].y
                 + iv.z * tv[p].z + iv.w * tv[p].w;
        pl += __shfl_xor_sync(0xffffffffu, pl, 1);
        pl += __shfl_xor_sync(0xffffffffu, pl, 2);
        pt += __shfl_xor_sync(0xffffffffu, pt, 1);
        pt += __shfl_xor_sync(0xffffffffu, pt, 2);
        const int s = p * 32 + quad;
        logit_s[s] = pl;
        td_s[s]    = pt;
    }
    __syncthreads();

    // ---- softmax over 64 slots per hop; thread t owns slot t ----
    const int hop = t >> 6;
    float logit = logit_s[t];
    float td    = td_s[t];

    float mx = logit;
    #pragma unroll
    for (int o = 16; o > 0; o >>= 1)
        mx = fmaxf(mx, __shfl_xor_sync(0xffffffffu, mx, o));
    if (lane == 0) red_s[wid] = mx;
    __syncthreads();
    mx = fmaxf(red_s[hop * 2], red_s[hop * 2 + 1]);

    float e = __expf(logit - mx);
    float sm = e;
    #pragma unroll
    for (int o = 16; o > 0; o >>= 1)
        sm += __shfl_xor_sync(0xffffffffu, sm, o);
    if (lane == 0) red_s[4 + wid] = sm;
    __syncthreads();
    sm = red_s[4 + hop * 2] + red_s[4 + hop * 2 + 1];

    const float pi = e / sm;

    // ---- contribution: pi * (tail . item); block-reduce ----
    float c = pi * td;
    #pragma unroll
    for (int o = 16; o > 0; o >>= 1)
        c += __shfl_xor_sync(0xffffffffu, c, o);
    __syncthreads();                 // protect red_s reuse
    if (lane == 0) red_s[wid] = c;
    __syncthreads();

    if (t == 0) {
        float total = red_s[0] + red_s[1] + red_s[2] + red_s[3];
        out[b] = 1.f / (1.f + __expf(-total));
    }
}

extern "C" void kernel_launch(void* const* d_in, const int* in_sizes, int n_in,
                              void* d_out, int out_size)
{
    const int*   items = (const int*)d_in[0];
    const int*   heads = (const int*)d_in[1];
    const int*   rels  = (const int*)d_in[2];
    const int*   tails = (const int*)d_in[3];
    const float* ent   = (const float*)d_in[4];
    const float* relm  = (const float*)d_in[5];
    float*       out   = (float*)d_out;

    qprep_kernel<<<NB / 4, 128>>>(items, ent, relm);
    ripple_kernel<<<NB, 128>>>(items, heads, rels, tails, ent, out);
}

// round 7
// speedup vs baseline: 1.6256x; 1.6256x over previous
#include <cuda_runtime.h>
#include <math.h>

#define NH 2
#define NB 2048
#define NM 64
#define ND 16
#define NREL 32

// Single fused kernel. 1024 blocks x 128 threads; each block handles 2 b's.
// Phase A: q[bb][r][j] = sum_i R[r][i][j]*item[bb][i] (vectorized relm reads, L2-hot)
// Phase B (x2): R3-style quad-split gathers + softmax + output.
__global__ __launch_bounds__(128)
void ripple_fused_kernel(const int* __restrict__ items,
                         const int* __restrict__ heads,
                         const int* __restrict__ rels,
                         const int* __restrict__ tails,
                         const float* __restrict__ ent,
                         const float* __restrict__ relm,
                         float* __restrict__ out)
{
    const int b0   = blockIdx.x * 2;
    const int t    = threadIdx.x;      // 0..127
    const int lane = t & 31;
    const int wid  = t >> 5;
    const int sub  = t & 3;            // position within quad
    const int quad = t >> 2;           // 0..31

    __shared__ __align__(16) float  item_s[2][ND];
    __shared__ __align__(16) float4 q_s[2][NREL * 4];   // [bb][r*4+jg]
    __shared__ float logit_s[NH * NM];
    __shared__ float td_s[NH * NM];
    __shared__ float red_s[8];

    // ---- Phase A0: load 2 item embeddings (32 floats) ----
    if (t < 2 * ND) {
        const int bb = t >> 4;
        const int d  = t & 15;
        item_s[bb][d] = ent[(size_t)items[b0 + bb] * ND + d];
    }
    __syncthreads();

    // ---- Phase A1: q-precompute; thread t owns (r = t>>2, jg = t&3) ----
    {
        const int r  = t >> 2;
        const int jg = t & 3;
        const float4* relm4 = (const float4*)relm;

        float4 a0 = make_float4(0.f, 0.f, 0.f, 0.f);
        float4 a1 = make_float4(0.f, 0.f, 0.f, 0.f);
        #pragma unroll
        for (int i = 0; i < ND; i++) {
            float4 Rv = relm4[r * 64 + i * 4 + jg];   // R[r][i][jg*4..+3]
            float s0 = item_s[0][i];
            float s1 = item_s[1][i];
            a0.x += s0 * Rv.x; a0.y += s0 * Rv.y; a0.z += s0 * Rv.z; a0.w += s0 * Rv.w;
            a1.x += s1 * Rv.x; a1.y += s1 * Rv.y; a1.z += s1 * Rv.z; a1.w += s1 * Rv.w;
        }
        q_s[0][t] = a0;    // t == r*4+jg
        q_s[1][t] = a1;
    }
    __syncthreads();

    const float4* ent4 = (const float4*)ent;

    // ---- Phase B: per-b gathers + softmax (R3-proven structure) ----
    for (int bb = 0; bb < 2; bb++) {
        const int b  = b0 + bb;
        const float4 iv = ((const float4*)item_s[bb])[sub];

        #pragma unroll
        for (int pass = 0; pass < 4; pass++) {
            const int s    = pass * 32 + quad;       // slot 0..127
            const int hop  = s >> 6;
            const int m    = s & 63;
            const int gidx = hop * (NB * NM) + b * NM + m;

            const int hidx = heads[gidx];
            const int ridx = rels[gidx];
            const int tidx = tails[gidx];

            float4 hv = ent4[(size_t)hidx * 4 + sub];
            float4 tv = ent4[(size_t)tidx * 4 + sub];
            float4 qv = q_s[bb][ridx * 4 + sub];

            float pl = qv.x * hv.x + qv.y * hv.y + qv.z * hv.z + qv.w * hv.w;
            float pt = iv.x * tv.x + iv.y * tv.y + iv.z * tv.z + iv.w * tv.w;

            pl += __shfl_xor_sync(0xffffffffu, pl, 1);
            pl += __shfl_xor_sync(0xffffffffu, pl, 2);
            pt += __shfl_xor_sync(0xffffffffu, pt, 1);
            pt += __shfl_xor_sync(0xffffffffu, pt, 2);

            logit_s[s] = pl;
            td_s[s]    = pt;
        }
        __syncthreads();

        // softmax over 64 slots per hop; thread t owns slot t
        const int hop = t >> 6;
        float logit = logit_s[t];
        float td    = td_s[t];

        float mx = logit;
        #pragma unroll
        for (int o = 16; o > 0; o >>= 1)
            mx = fmaxf(mx, __shfl_xor_sync(0xffffffffu, mx, o));
        if (lane == 0) red_s[wid] = mx;
        __syncthreads();
        mx = fmaxf(red_s[hop * 2], red_s[hop * 2 + 1]);

        float e = __expf(logit - mx);
        float sm = e;
        #pragma unroll
        for (int o = 16; o > 0; o >>= 1)
            sm += __shfl_xor_sync(0xffffffffu, sm, o);
        if (lane == 0) red_s[4 + wid] = sm;
        __syncthreads();
        sm = red_s[4 + hop * 2] + red_s[4 + hop * 2 + 1];

        const float pi = e / sm;

        float c = pi * td;
        #pragma unroll
        for (int o = 16; o > 0; o >>= 1)
            c += __shfl_xor_sync(0xffffffffu, c, o);
        __syncthreads();                 // protect red_s reuse
        if (lane == 0) red_s[wid] = c;
        __syncthreads();

        if (t == 0) {
            float total = red_s[0] + red_s[1] + red_s[2] + red_s[3];
            out[b] = 1.f / (1.f + __expf(-total));
        }
        __syncthreads();                 // out-read of red_s before next bb's writes
    }
}

extern "C" void kernel_launch(void* const* d_in, const int* in_sizes, int n_in,
                              void* d_out, int out_size)
{
    const int*   items = (const int*)d_in[0];
    const int*   heads = (const int*)d_in[1];
    const int*   rels  = (const int*)d_in[2];
    const int*   tails = (const int*)d_in[3];
    const float* ent   = (const float*)d_in[4];
    const float* relm  = (const float*)d_in[5];
    float*       out   = (float*)d_out;

    ripple_fused_kernel<<<NB / 2, 128>>>(items, heads, rels, tails, ent, relm, out);
}